// round 6
// baseline (speedup 1.0000x reference)
#include <cuda_runtime.h>
#include <cuda_fp16.h>
#include <cstdint>

#define D_MODEL   1024
#define NUM_HEADS 16
#define HEAD_DIM  64
#define SEQ       2048
#define BATCH     2
#define MTOT      (BATCH * SEQ)

// ---------------------------------------------------------------------------
// Scratch (device globals; allocation forbidden)
// ---------------------------------------------------------------------------
__device__ __half g_q [BATCH * NUM_HEADS * SEQ * HEAD_DIM];
__device__ __half g_k [BATCH * NUM_HEADS * SEQ * HEAD_DIM];
__device__ __half g_v [BATCH * NUM_HEADS * SEQ * HEAD_DIM];
__device__ __half g_ao[MTOT * D_MODEL];
__device__ __half g_xh[MTOT * D_MODEL];
__device__ __half g_wq[D_MODEL * D_MODEL];
__device__ __half g_wk[D_MODEL * D_MODEL];
__device__ __half g_wv[D_MODEL * D_MODEL];
__device__ __half g_wo[D_MODEL * D_MODEL];

// ---------------------------------------------------------------------------
// Helpers
// ---------------------------------------------------------------------------
__device__ __forceinline__ float ex2f(float x) {
    float y;
    asm("ex2.approx.f32 %0, %1;" : "=f"(y) : "f"(x));
    return y;
}

__device__ __forceinline__ void mma16(float c[4], const unsigned a[4],
                                      unsigned b0, unsigned b1) {
    asm volatile(
        "mma.sync.aligned.m16n8k16.row.col.f32.f16.f16.f32 "
        "{%0,%1,%2,%3},{%4,%5,%6,%7},{%8,%9},{%0,%1,%2,%3};"
        : "+f"(c[0]), "+f"(c[1]), "+f"(c[2]), "+f"(c[3])
        : "r"(a[0]), "r"(a[1]), "r"(a[2]), "r"(a[3]), "r"(b0), "r"(b1));
}

__device__ __forceinline__ void cp16(void* sdst, const void* gsrc) {
    unsigned s = (unsigned)__cvta_generic_to_shared(sdst);
    asm volatile("cp.async.cg.shared.global [%0], [%1], 16;\n"
                 :: "r"(s), "l"(gsrc));
}

__device__ __forceinline__ void ldsm4(unsigned& r0, unsigned& r1,
                                      unsigned& r2, unsigned& r3,
                                      unsigned addr) {
    asm volatile(
        "ldmatrix.sync.aligned.m8n8.x4.shared.b16 {%0,%1,%2,%3}, [%4];"
        : "=r"(r0), "=r"(r1), "=r"(r2), "=r"(r3) : "r"(addr));
}

__device__ __forceinline__ void ldsm4t(unsigned& r0, unsigned& r1,
                                       unsigned& r2, unsigned& r3,
                                       unsigned addr) {
    asm volatile(
        "ldmatrix.sync.aligned.m8n8.x4.trans.shared.b16 {%0,%1,%2,%3}, [%4];"
        : "=r"(r0), "=r"(r1), "=r"(r2), "=r"(r3) : "r"(addr));
}

__device__ __forceinline__ unsigned h2u(__half2 h) {
    return *reinterpret_cast<unsigned*>(&h);
}

// ---------------------------------------------------------------------------
// Fused fp32 -> fp16 convert
// ---------------------------------------------------------------------------
#define NX4 (MTOT * D_MODEL / 4)
#define NW4 (D_MODEL * D_MODEL / 4)

__global__ void to_half_all(
    const float4* __restrict__ x,  const float4* __restrict__ wq,
    const float4* __restrict__ wk, const float4* __restrict__ wv,
    const float4* __restrict__ wo,
    uint2* __restrict__ xh, uint2* __restrict__ oq, uint2* __restrict__ ok,
    uint2* __restrict__ ov, uint2* __restrict__ oo)
{
    const int total = NX4 + 4 * NW4;
    for (int i = blockIdx.x * blockDim.x + threadIdx.x; i < total;
         i += gridDim.x * blockDim.x) {
        const float4* src;
        uint2* dst;
        int off;
        if (i < NX4) { src = x; dst = xh; off = i; }
        else {
            const int j = i - NX4, w = j >> 18;
            off = j & (NW4 - 1);
            src = (w == 0) ? wq : (w == 1) ? wk : (w == 2) ? wv : wo;
            dst = (w == 0) ? oq : (w == 1) ? ok : (w == 2) ? ov : oo;
        }
        float4 v = src[off];
        uint2 o;
        o.x = h2u(__floats2half2_rn(v.x, v.y));
        o.y = h2u(__floats2half2_rn(v.z, v.w));
        dst[off] = o;
    }
}

// ---------------------------------------------------------------------------
// NT GEMM (fp16 in / fp32 accum), CTA tile 128(m) x 256(n), 512 threads =
// 16 warps (4m x 4n), warp tile 32x64.  K-chunk 64, 2-stage cp.async,
// ldmatrix fragment loads.
// QKV=1: fused Q/K/V projection — blockIdx.x selects weight (4 CTAs each),
//        fp16 scatter to [B,H,S,hd].
// QKV=0: O-projection — fp32 row-major out.
// ---------------------------------------------------------------------------
#define GSA    36                          // words per 64-half row (+pad)
#define GROWB  144                         // bytes per row
#define STAGEW ((128 + 256) * GSA)         // words per stage
#define GSMEM_BYTES (2 * STAGEW * 4)       // 110592

template <int QKV>
__global__ __launch_bounds__(512)
void gemm_h(const __half* __restrict__ A,
            const __half* __restrict__ W0, const __half* __restrict__ W1,
            const __half* __restrict__ W2,
            const float* __restrict__ b0p, const float* __restrict__ b1p,
            const float* __restrict__ b2p,
            void* __restrict__ C0, void* __restrict__ C1,
            void* __restrict__ C2)
{
    extern __shared__ unsigned sm[];
    const unsigned smem_byte = (unsigned)__cvta_generic_to_shared(sm);
    const int tid = threadIdx.x, lane = tid & 31, wid = tid >> 5;
    const int wm = wid & 3, wn = wid >> 2;            // 4 x 4 warps
    const int m0 = blockIdx.y * 128;

    const int wsel = QKV ? (blockIdx.x >> 2) : 0;
    const int n0   = QKV ? (blockIdx.x & 3) * 256 : blockIdx.x * 256;
    const __half* W = (wsel == 0) ? W0 : (wsel == 1) ? W1 : W2;
    const float* bias = (wsel == 0) ? b0p : (wsel == 1) ? b1p : b2p;
    void* Cv = (wsel == 0) ? C0 : (wsel == 1) ? C1 : C2;

    float acc[2][8][4];
#pragma unroll
    for (int i = 0; i < 2; i++)
#pragma unroll
        for (int j = 0; j < 8; j++)
#pragma unroll
            for (int e = 0; e < 4; e++) acc[i][j][e] = 0.f;

    auto issue = [&](int s, int k0) {
        unsigned* dA = sm + s * STAGEW;
        unsigned* dB = dA + 128 * GSA;
        const __half* Ap = A + (size_t)m0 * D_MODEL + k0;
        const __half* Bp = W + (size_t)n0 * D_MODEL + k0;
#pragma unroll
        for (int i = 0; i < 2; i++) {           // A: 128 rows x 8 chunks
            const int lin = tid + i * 512;
            const int r = lin >> 3, c8 = lin & 7;
            cp16(dA + r * GSA + c8 * 4, Ap + (size_t)r * D_MODEL + c8 * 8);
        }
#pragma unroll
        for (int i = 0; i < 4; i++) {           // B: 256 rows x 8 chunks
            const int lin = tid + i * 512;
            const int r = lin >> 3, c8 = lin & 7;
            cp16(dB + r * GSA + c8 * 4, Bp + (size_t)r * D_MODEL + c8 * 8);
        }
        asm volatile("cp.async.commit_group;\n" ::: "memory");
    };

    const unsigned a_lane =
        (unsigned)((wm * 32 + (lane & 15)) * GROWB + (lane >> 4) * 16);
    const unsigned b_lane =
        (unsigned)((wn * 64 + ((lane >> 3) & 1) * 8 + (lane & 7)) * GROWB
                   + (lane >> 4) * 16);

    issue(0, 0);
    const int T = D_MODEL / 64;   // 16 chunks
    for (int tt = 0; tt < T; tt++) {
        const int s = tt & 1;
        if (tt + 1 < T) {
            issue(s ^ 1, (tt + 1) * 64);
            asm volatile("cp.async.wait_group 1;\n" ::: "memory");
        } else {
            asm volatile("cp.async.wait_group 0;\n" ::: "memory");
        }
        __syncthreads();

        const unsigned aBase = smem_byte + s * STAGEW * 4 + a_lane;
        const unsigned bBase = smem_byte + s * STAGEW * 4 + 128 * GROWB + b_lane;
#pragma unroll
        for (int kk = 0; kk < 4; kk++) {
            unsigned af[2][4], bf[8][2];
#pragma unroll
            for (int mt = 0; mt < 2; mt++)
                ldsm4(af[mt][0], af[mt][1], af[mt][2], af[mt][3],
                      aBase + mt * 16 * GROWB + kk * 32);
#pragma unroll
            for (int p = 0; p < 4; p++) {
                unsigned r0, r1, r2, r3;
                ldsm4(r0, r1, r2, r3, bBase + p * 16 * GROWB + kk * 32);
                bf[2 * p][0] = r0; bf[2 * p + 1][0] = r1;
                bf[2 * p][1] = r2; bf[2 * p + 1][1] = r3;
            }
#pragma unroll
            for (int mt = 0; mt < 2; mt++)
#pragma unroll
                for (int nt = 0; nt < 8; nt++)
                    mma16(acc[mt][nt], af[mt], bf[nt][0], bf[nt][1]);
        }
        __syncthreads();
    }

    // epilogue
    const int g = lane >> 2, t = lane & 3;
#pragma unroll
    for (int mt = 0; mt < 2; mt++) {
#pragma unroll
        for (int nt = 0; nt < 8; nt++) {
            const int row = m0 + wm * 32 + mt * 16 + g;
            const int col = n0 + wn * 64 + nt * 8 + 2 * t;
            const float bv0 = bias[col], bv1 = bias[col + 1];
#pragma unroll
            for (int hf = 0; hf < 2; hf++) {
                const int r = row + hf * 8;
                const float vx = acc[mt][nt][hf * 2 + 0] + bv0;
                const float vy = acc[mt][nt][hf * 2 + 1] + bv1;
                if (QKV == 0) {
                    float* C = (float*)Cv;
                    *reinterpret_cast<float2*>(C + (size_t)r * D_MODEL + col) =
                        make_float2(vx, vy);
                } else {
                    __half* C = (__half*)Cv;
                    const int bb = r >> 11, ss = r & (SEQ - 1);
                    const int hh = col >> 6, dd = col & (HEAD_DIM - 1);
                    *reinterpret_cast<unsigned*>(
                        C + (((size_t)(bb * NUM_HEADS + hh) * SEQ + ss) << 6)
                          + dd) = h2u(__floats2half2_rn(vx, vy));
                }
            }
        }
    }
}

// ---------------------------------------------------------------------------
// Flash attention (causal).  Block = (b, h, 128-row q tile), 4 warps.
// (unchanged from R5 — passing, profiled next)
// ---------------------------------------------------------------------------
#define KS_OFF (128 * GSA)
#define VS_OFF (KS_OFF + 2 * 64 * GSA)
#define KVSTGW (64 * GSA)
#define A_SMEM_BYTES ((VS_OFF + 2 * 64 * GSA) * 4)   // 55296

__global__ __launch_bounds__(128)
void attn_kernel(const __half* __restrict__ gq, const __half* __restrict__ gk,
                 const __half* __restrict__ gv, __half* __restrict__ gout)
{
    extern __shared__ unsigned smu[];
    unsigned* Ps = smu;
    const unsigned smem_byte = (unsigned)__cvta_generic_to_shared(smu);

    const int tid  = threadIdx.x;
    const int lane = tid & 31, w = tid >> 5;
    const int g = lane >> 2, t = lane & 3;
    const int qt = gridDim.x - 1 - blockIdx.x;
    const int h = blockIdx.y, b = blockIdx.z;

    const size_t base = (size_t)(b * NUM_HEADS + h) * SEQ * HEAD_DIM;
    const __half* Q  = gq + base + (size_t)qt * 128 * HEAD_DIM;
    const __half* Kp = gk + base;
    const __half* Vp = gv + base;

    for (int i = tid; i < 128 * 8; i += 128) {
        const int r = i >> 3, c8 = i & 7;
        uint4 v4 = reinterpret_cast<const uint4*>(Q + r * HEAD_DIM)[c8];
        *reinterpret_cast<uint4*>(&Ps[r * GSA + c8 * 4]) = v4;
    }
    __syncthreads();

    const unsigned amat_lane =
        (unsigned)((w * 32 + (lane & 15)) * GROWB + (lane >> 4) * 16);
    unsigned qf[4][2][4];
#pragma unroll
    for (int kk = 0; kk < 4; kk++)
#pragma unroll
        for (int mt = 0; mt < 2; mt++)
            ldsm4(qf[kk][mt][0], qf[kk][mt][1], qf[kk][mt][2], qf[kk][mt][3],
                  smem_byte + amat_lane + mt * 16 * GROWB + kk * 32);
    __syncthreads();

    float oacc[2][8][4];
#pragma unroll
    for (int mt = 0; mt < 2; mt++)
#pragma unroll
        for (int i = 0; i < 8; i++)
#pragma unroll
            for (int e = 0; e < 4; e++) oacc[mt][i][e] = 0.f;

    float mr[4], ls[4];
#pragma unroll
    for (int i = 0; i < 4; i++) { mr[i] = -1e30f; ls[i] = 0.f; }

    const float sl = 0.125f * 1.4426950408889634f;
    const int njt = 2 * qt + 2;

    auto issueKV = [&](int s, int j) {
        const __half* Kj = Kp + (size_t)j * 64 * HEAD_DIM;
        const __half* Vj = Vp + (size_t)j * 64 * HEAD_DIM;
        unsigned* dK = smu + KS_OFF + s * KVSTGW;
        unsigned* dV = smu + VS_OFF + s * KVSTGW;
#pragma unroll
        for (int i = 0; i < 4; i++) {
            const int lin = tid + i * 128;
            const int r = lin >> 3, c8 = lin & 7;
            cp16(dK + r * GSA + c8 * 4, Kj + r * HEAD_DIM + c8 * 8);
        }
#pragma unroll
        for (int i = 0; i < 4; i++) {
            const int lin = tid + i * 128;
            const int r = lin >> 3, c8 = lin & 7;
            cp16(dV + r * GSA + c8 * 4, Vj + r * HEAD_DIM + c8 * 8);
        }
        asm volatile("cp.async.commit_group;\n" ::: "memory");
    };

    const unsigned bmat_lane =
        (unsigned)((((lane >> 3) & 1) * 8 + (lane & 7)) * GROWB
                   + (lane >> 4) * 16);
    const unsigned vmat_lane =
        (unsigned)((((lane >> 3) & 1) * 8 + (lane & 7)) * GROWB
                   + (lane >> 4) * 16);

    issueKV(0, 0);
    for (int j = 0; j < njt; j++) {
        const int s = j & 1;
        if (j + 1 < njt) {
            issueKV(s ^ 1, j + 1);
            asm volatile("cp.async.wait_group 1;\n" ::: "memory");
        } else {
            asm volatile("cp.async.wait_group 0;\n" ::: "memory");
        }
        __syncthreads();

        const unsigned ksb = smem_byte + (KS_OFF + s * KVSTGW) * 4;
        const unsigned vsb = smem_byte + (VS_OFF + s * KVSTGW) * 4;

        float sacc[2][8][4];
#pragma unroll
        for (int mt = 0; mt < 2; mt++)
#pragma unroll
            for (int i = 0; i < 8; i++)
#pragma unroll
                for (int e = 0; e < 4; e++) sacc[mt][i][e] = 0.f;

#pragma unroll
        for (int kk = 0; kk < 4; kk++) {
            unsigned bf[8][2];
#pragma unroll
            for (int p = 0; p < 4; p++) {
                unsigned r0, r1, r2, r3;
                ldsm4(r0, r1, r2, r3,
                      ksb + bmat_lane + p * 16 * GROWB + kk * 32);
                bf[2 * p][0] = r0; bf[2 * p + 1][0] = r1;
                bf[2 * p][1] = r2; bf[2 * p + 1][1] = r3;
            }
#pragma unroll
            for (int nt = 0; nt < 8; nt++) {
                mma16(sacc[0][nt], qf[kk][0], bf[nt][0], bf[nt][1]);
                mma16(sacc[1][nt], qf[kk][1], bf[nt][0], bf[nt][1]);
            }
        }

        if (j >= 2 * qt) {
#pragma unroll
            for (int mt = 0; mt < 2; mt++)
#pragma unroll
                for (int nt = 0; nt < 8; nt++)
#pragma unroll
                    for (int e = 0; e < 4; e++) {
                        const int colg = j * 64 + nt * 8 + 2 * t + (e & 1);
                        const int rowg = qt * 128 + w * 32 + mt * 16 + g
                                       + ((e >> 1) << 3);
                        sacc[mt][nt][e] = (colg > rowg) ? -1e30f
                                                        : sacc[mt][nt][e] * sl;
                    }
        } else {
#pragma unroll
            for (int mt = 0; mt < 2; mt++)
#pragma unroll
                for (int nt = 0; nt < 8; nt++)
#pragma unroll
                    for (int e = 0; e < 4; e++) sacc[mt][nt][e] *= sl;
        }

#pragma unroll
        for (int mt = 0; mt < 2; mt++) {
            float mx0 = -1e30f, mx1 = -1e30f;
#pragma unroll
            for (int nt = 0; nt < 8; nt++) {
                mx0 = fmaxf(mx0, fmaxf(sacc[mt][nt][0], sacc[mt][nt][1]));
                mx1 = fmaxf(mx1, fmaxf(sacc[mt][nt][2], sacc[mt][nt][3]));
            }
            mx0 = fmaxf(mx0, __shfl_xor_sync(0xffffffffu, mx0, 1));
            mx0 = fmaxf(mx0, __shfl_xor_sync(0xffffffffu, mx0, 2));
            mx1 = fmaxf(mx1, __shfl_xor_sync(0xffffffffu, mx1, 1));
            mx1 = fmaxf(mx1, __shfl_xor_sync(0xffffffffu, mx1, 2));
            const float nm0 = fmaxf(mr[mt * 2 + 0], mx0);
            const float nm1 = fmaxf(mr[mt * 2 + 1], mx1);
            const float al0 = ex2f(mr[mt * 2 + 0] - nm0);
            const float al1 = ex2f(mr[mt * 2 + 1] - nm1);
            mr[mt * 2 + 0] = nm0; mr[mt * 2 + 1] = nm1;

            const int prow = w * 32 + mt * 16 + g;
            float ps0 = 0.f, ps1 = 0.f;
#pragma unroll
            for (int nt = 0; nt < 8; nt++) {
                const float p0 = ex2f(sacc[mt][nt][0] - nm0);
                const float p1 = ex2f(sacc[mt][nt][1] - nm0);
                const float p2 = ex2f(sacc[mt][nt][2] - nm1);
                const float p3 = ex2f(sacc[mt][nt][3] - nm1);
                ps0 += p0 + p1; ps1 += p2 + p3;
                Ps[ prow      * GSA + nt * 4 + t] = h2u(__floats2half2_rn(p0, p1));
                Ps[(prow + 8) * GSA + nt * 4 + t] = h2u(__floats2half2_rn(p2, p3));
            }
            ps0 += __shfl_xor_sync(0xffffffffu, ps0, 1);
            ps0 += __shfl_xor_sync(0xffffffffu, ps0, 2);
            ps1 += __shfl_xor_sync(0xffffffffu, ps1, 1);
            ps1 += __shfl_xor_sync(0xffffffffu, ps1, 2);
            ls[mt * 2 + 0] = ls[mt * 2 + 0] * al0 + ps0;
            ls[mt * 2 + 1] = ls[mt * 2 + 1] * al1 + ps1;
#pragma unroll
            for (int nt = 0; nt < 8; nt++) {
                oacc[mt][nt][0] *= al0; oacc[mt][nt][1] *= al0;
                oacc[mt][nt][2] *= al1; oacc[mt][nt][3] *= al1;
            }
        }
        __syncwarp();

#pragma unroll
        for (int kk = 0; kk < 4; kk++) {
            unsigned pa[2][4];
#pragma unroll
            for (int mt = 0; mt < 2; mt++)
                ldsm4(pa[mt][0], pa[mt][1], pa[mt][2], pa[mt][3],
                      smem_byte + amat_lane + mt * 16 * GROWB + kk * 32);
#pragma unroll
            for (int p = 0; p < 4; p++) {
                unsigned r0, r1, r2, r3;
                ldsm4t(r0, r1, r2, r3,
                       vsb + (unsigned)(kk * 16) * GROWB + vmat_lane
                           + (unsigned)(2 * p) * 16);
                mma16(oacc[0][2 * p    ], pa[0], r0, r1);
                mma16(oacc[1][2 * p    ], pa[1], r0, r1);
                mma16(oacc[0][2 * p + 1], pa[0], r2, r3);
                mma16(oacc[1][2 * p + 1], pa[1], r2, r3);
            }
        }
        __syncthreads();
    }

#pragma unroll
    for (int mt = 0; mt < 2; mt++) {
        const float il0 = 1.f / ls[mt * 2 + 0];
        const float il1 = 1.f / ls[mt * 2 + 1];
        const int qrow = qt * 128 + w * 32 + mt * 16 + g;
        __half* O0 = gout + (size_t)(b * SEQ + qrow) * D_MODEL + h * HEAD_DIM;
        __half* O1 = O0 + 8 * D_MODEL;
#pragma unroll
        for (int nt = 0; nt < 8; nt++) {
            const int col = nt * 8 + 2 * t;
            *reinterpret_cast<unsigned*>(O0 + col) =
                h2u(__floats2half2_rn(oacc[mt][nt][0] * il0,
                                      oacc[mt][nt][1] * il0));
            *reinterpret_cast<unsigned*>(O1 + col) =
                h2u(__floats2half2_rn(oacc[mt][nt][2] * il1,
                                      oacc[mt][nt][3] * il1));
        }
    }
}

// ---------------------------------------------------------------------------
// Launch
// ---------------------------------------------------------------------------
extern "C" void kernel_launch(void* const* d_in, const int* in_sizes, int n_in,
                              void* d_out, int out_size)
{
    const float* x  = (const float*)d_in[0];
    const float* Wq = (const float*)d_in[1];
    const float* bq = (const float*)d_in[2];
    const float* Wk = (const float*)d_in[3];
    const float* bk = (const float*)d_in[4];
    const float* Wv = (const float*)d_in[5];
    const float* bv = (const float*)d_in[6];
    const float* Wo = (const float*)d_in[7];
    const float* bo = (const float*)d_in[8];
    float* out = (float*)d_out;

    __half *q, *k, *v, *ao, *xh, *wq, *wk, *wv, *wo;
    cudaGetSymbolAddress((void**)&q,  g_q);
    cudaGetSymbolAddress((void**)&k,  g_k);
    cudaGetSymbolAddress((void**)&v,  g_v);
    cudaGetSymbolAddress((void**)&ao, g_ao);
    cudaGetSymbolAddress((void**)&xh, g_xh);
    cudaGetSymbolAddress((void**)&wq, g_wq);
    cudaGetSymbolAddress((void**)&wk, g_wk);
    cudaGetSymbolAddress((void**)&wv, g_wv);
    cudaGetSymbolAddress((void**)&wo, g_wo);

    to_half_all<<<2048, 256>>>((const float4*)x,  (const float4*)Wq,
                               (const float4*)Wk, (const float4*)Wv,
                               (const float4*)Wo,
                               (uint2*)xh, (uint2*)wq, (uint2*)wk,
                               (uint2*)wv, (uint2*)wo);

    cudaFuncSetAttribute(gemm_h<0>,
        cudaFuncAttributeMaxDynamicSharedMemorySize, GSMEM_BYTES);
    cudaFuncSetAttribute(gemm_h<1>,
        cudaFuncAttributeMaxDynamicSharedMemorySize, GSMEM_BYTES);
    cudaFuncSetAttribute(attn_kernel,
        cudaFuncAttributeMaxDynamicSharedMemorySize, A_SMEM_BYTES);

    // fused QKV: 12 x 32 = 384 CTAs, each CTA serves one weight
    const dim3 qkvgrid(3 * D_MODEL / 256, MTOT / 128);
    gemm_h<1><<<qkvgrid, 512, GSMEM_BYTES>>>(
        xh, wq, wk, wv, bq, bk, bv, q, k, v);

    const dim3 agrid(SEQ / 128, NUM_HEADS, BATCH);
    attn_kernel<<<agrid, 128, A_SMEM_BYTES>>>(q, k, v, ao);

    const dim3 ogrid(D_MODEL / 256, MTOT / 128);
    gemm_h<0><<<ogrid, 512, GSMEM_BYTES>>>(
        ao, wo, wo, wo, bo, bo, bo, out, out, out);
}

// round 7
// speedup vs baseline: 1.0316x; 1.0316x over previous
#include <cuda_runtime.h>
#include <cuda_fp16.h>
#include <cstdint>

#define D_MODEL   1024
#define NUM_HEADS 16
#define HEAD_DIM  64
#define SEQ       2048
#define BATCH     2
#define MTOT      (BATCH * SEQ)

// ---------------------------------------------------------------------------
// Scratch (device globals; allocation forbidden)
// ---------------------------------------------------------------------------
__device__ __half g_q [BATCH * NUM_HEADS * SEQ * HEAD_DIM];
__device__ __half g_k [BATCH * NUM_HEADS * SEQ * HEAD_DIM];
__device__ __half g_v [BATCH * NUM_HEADS * SEQ * HEAD_DIM];
__device__ __half g_ao[MTOT * D_MODEL];
__device__ __half g_xh[MTOT * D_MODEL];
__device__ __half g_wq[D_MODEL * D_MODEL];
__device__ __half g_wk[D_MODEL * D_MODEL];
__device__ __half g_wv[D_MODEL * D_MODEL];
__device__ __half g_wo[D_MODEL * D_MODEL];

// ---------------------------------------------------------------------------
// Helpers
// ---------------------------------------------------------------------------
__device__ __forceinline__ float ex2f(float x) {
    float y;
    asm("ex2.approx.f32 %0, %1;" : "=f"(y) : "f"(x));
    return y;
}

__device__ __forceinline__ void mma16(float c[4], const unsigned a[4],
                                      unsigned b0, unsigned b1) {
    asm volatile(
        "mma.sync.aligned.m16n8k16.row.col.f32.f16.f16.f32 "
        "{%0,%1,%2,%3},{%4,%5,%6,%7},{%8,%9},{%0,%1,%2,%3};"
        : "+f"(c[0]), "+f"(c[1]), "+f"(c[2]), "+f"(c[3])
        : "r"(a[0]), "r"(a[1]), "r"(a[2]), "r"(a[3]), "r"(b0), "r"(b1));
}

__device__ __forceinline__ void cp16(void* sdst, const void* gsrc) {
    unsigned s = (unsigned)__cvta_generic_to_shared(sdst);
    asm volatile("cp.async.cg.shared.global [%0], [%1], 16;\n"
                 :: "r"(s), "l"(gsrc));
}

__device__ __forceinline__ void ldsm4(unsigned& r0, unsigned& r1,
                                      unsigned& r2, unsigned& r3,
                                      unsigned addr) {
    asm volatile(
        "ldmatrix.sync.aligned.m8n8.x4.shared.b16 {%0,%1,%2,%3}, [%4];"
        : "=r"(r0), "=r"(r1), "=r"(r2), "=r"(r3) : "r"(addr));
}

__device__ __forceinline__ void ldsm4t(unsigned& r0, unsigned& r1,
                                       unsigned& r2, unsigned& r3,
                                       unsigned addr) {
    asm volatile(
        "ldmatrix.sync.aligned.m8n8.x4.trans.shared.b16 {%0,%1,%2,%3}, [%4];"
        : "=r"(r0), "=r"(r1), "=r"(r2), "=r"(r3) : "r"(addr));
}

__device__ __forceinline__ unsigned h2u(__half2 h) {
    return *reinterpret_cast<unsigned*>(&h);
}

// ---------------------------------------------------------------------------
// Fused fp32 -> fp16 convert
// ---------------------------------------------------------------------------
#define NX4 (MTOT * D_MODEL / 4)
#define NW4 (D_MODEL * D_MODEL / 4)

__global__ void to_half_all(
    const float4* __restrict__ x,  const float4* __restrict__ wq,
    const float4* __restrict__ wk, const float4* __restrict__ wv,
    const float4* __restrict__ wo,
    uint2* __restrict__ xh, uint2* __restrict__ oq, uint2* __restrict__ ok,
    uint2* __restrict__ ov, uint2* __restrict__ oo)
{
    const int total = NX4 + 4 * NW4;
    for (int i = blockIdx.x * blockDim.x + threadIdx.x; i < total;
         i += gridDim.x * blockDim.x) {
        const float4* src;
        uint2* dst;
        int off;
        if (i < NX4) { src = x; dst = xh; off = i; }
        else {
            const int j = i - NX4, w = j >> 18;
            off = j & (NW4 - 1);
            src = (w == 0) ? wq : (w == 1) ? wk : (w == 2) ? wv : wo;
            dst = (w == 0) ? oq : (w == 1) ? ok : (w == 2) ? ov : oo;
        }
        float4 v = src[off];
        uint2 o;
        o.x = h2u(__floats2half2_rn(v.x, v.y));
        o.y = h2u(__floats2half2_rn(v.z, v.w));
        dst[off] = o;
    }
}

// ---------------------------------------------------------------------------
// NT GEMM (fp16 in / fp32 accum): C[m,n] = sum_k A[m,k]*W[n,k] + bias[n]
// CTA tile 128x128, 128 threads = 4 warps (2x2), warp tile 64x64.
// 3-stage cp.async ring, ONE __syncthreads per K-chunk, 2 CTAs/SM.
// QKV=1: blockIdx.x = wsel*8 + ntile; fp16 scatter to [B,H,S,hd].
// QKV=0: fp32 row-major out.
// ---------------------------------------------------------------------------
#define GSA    36                          // words per 64-half row (+pad)
#define GROWB  144                         // bytes per row
#define STAGEW ((128 + 128) * GSA)         // 9216 words per stage
#define NSTG   3
#define GSMEM_BYTES (NSTG * STAGEW * 4)    // 110592

template <int QKV>
__global__ __launch_bounds__(128, 2)
void gemm_h(const __half* __restrict__ A,
            const __half* __restrict__ W0, const __half* __restrict__ W1,
            const __half* __restrict__ W2,
            const float* __restrict__ b0p, const float* __restrict__ b1p,
            const float* __restrict__ b2p,
            void* __restrict__ C0, void* __restrict__ C1,
            void* __restrict__ C2)
{
    extern __shared__ unsigned sm[];
    const unsigned smem_byte = (unsigned)__cvta_generic_to_shared(sm);
    const int tid = threadIdx.x, lane = tid & 31, wid = tid >> 5;
    const int wm = wid & 1, wn = wid >> 1;            // 2 x 2 warps
    const int m0 = blockIdx.y * 128;

    const int wsel = QKV ? (blockIdx.x >> 3) : 0;
    const int n0   = QKV ? (blockIdx.x & 7) * 128 : blockIdx.x * 128;
    const __half* W = (wsel == 0) ? W0 : (wsel == 1) ? W1 : W2;
    const float* bias = (wsel == 0) ? b0p : (wsel == 1) ? b1p : b2p;
    void* Cv = (wsel == 0) ? C0 : (wsel == 1) ? C1 : C2;

    float acc[4][8][4];
#pragma unroll
    for (int i = 0; i < 4; i++)
#pragma unroll
        for (int j = 0; j < 8; j++)
#pragma unroll
            for (int e = 0; e < 4; e++) acc[i][j][e] = 0.f;

    auto issue = [&](int s, int k0) {
        unsigned* dA = sm + s * STAGEW;
        unsigned* dB = dA + 128 * GSA;
        const __half* Ap = A + (size_t)m0 * D_MODEL + k0;
        const __half* Bp = W + (size_t)n0 * D_MODEL + k0;
#pragma unroll
        for (int i = 0; i < 8; i++) {           // 128 rows x 8 chunks each
            const int lin = tid + i * 128;
            const int r = lin >> 3, c8 = lin & 7;
            cp16(dA + r * GSA + c8 * 4, Ap + (size_t)r * D_MODEL + c8 * 8);
            cp16(dB + r * GSA + c8 * 4, Bp + (size_t)r * D_MODEL + c8 * 8);
        }
        asm volatile("cp.async.commit_group;\n" ::: "memory");
    };

    const unsigned a_lane =
        (unsigned)((wm * 64 + (lane & 15)) * GROWB + (lane >> 4) * 16);
    const unsigned b_lane =
        (unsigned)((wn * 64 + ((lane >> 3) & 1) * 8 + (lane & 7)) * GROWB
                   + (lane >> 4) * 16);

    issue(0, 0);
    issue(1, 64);
    const int T = D_MODEL / 64;   // 16 chunks
    for (int tt = 0; tt < T; tt++) {
        const int s = tt % NSTG;
        if (tt + 1 < T) {
            asm volatile("cp.async.wait_group 1;\n" ::: "memory");
        } else {
            asm volatile("cp.async.wait_group 0;\n" ::: "memory");
        }
        __syncthreads();   // stage tt ready AND all warps done with tt-1
        if (tt + 2 < T) issue((tt + 2) % NSTG, (tt + 2) * 64);

        const unsigned aBase = smem_byte + s * STAGEW * 4 + a_lane;
        const unsigned bBase = smem_byte + s * STAGEW * 4 + 128 * GROWB + b_lane;
#pragma unroll
        for (int kk = 0; kk < 4; kk++) {
            unsigned af[4][4], bf[8][2];
#pragma unroll
            for (int mt = 0; mt < 4; mt++)
                ldsm4(af[mt][0], af[mt][1], af[mt][2], af[mt][3],
                      aBase + mt * 16 * GROWB + kk * 32);
#pragma unroll
            for (int p = 0; p < 4; p++) {
                unsigned r0, r1, r2, r3;
                ldsm4(r0, r1, r2, r3, bBase + p * 16 * GROWB + kk * 32);
                bf[2 * p][0] = r0; bf[2 * p + 1][0] = r1;
                bf[2 * p][1] = r2; bf[2 * p + 1][1] = r3;
            }
#pragma unroll
            for (int mt = 0; mt < 4; mt++)
#pragma unroll
                for (int nt = 0; nt < 8; nt++)
                    mma16(acc[mt][nt], af[mt], bf[nt][0], bf[nt][1]);
        }
    }

    // epilogue
    const int g = lane >> 2, t = lane & 3;
#pragma unroll
    for (int mt = 0; mt < 4; mt++) {
#pragma unroll
        for (int nt = 0; nt < 8; nt++) {
            const int row = m0 + wm * 64 + mt * 16 + g;
            const int col = n0 + wn * 64 + nt * 8 + 2 * t;
            const float bv0 = bias[col], bv1 = bias[col + 1];
#pragma unroll
            for (int hf = 0; hf < 2; hf++) {
                const int r = row + hf * 8;
                const float vx = acc[mt][nt][hf * 2 + 0] + bv0;
                const float vy = acc[mt][nt][hf * 2 + 1] + bv1;
                if (QKV == 0) {
                    float* C = (float*)Cv;
                    *reinterpret_cast<float2*>(C + (size_t)r * D_MODEL + col) =
                        make_float2(vx, vy);
                } else {
                    __half* C = (__half*)Cv;
                    const int bb = r >> 11, ss = r & (SEQ - 1);
                    const int hh = col >> 6, dd = col & (HEAD_DIM - 1);
                    *reinterpret_cast<unsigned*>(
                        C + (((size_t)(bb * NUM_HEADS + hh) * SEQ + ss) << 6)
                          + dd) = h2u(__floats2half2_rn(vx, vy));
                }
            }
        }
    }
}

// ---------------------------------------------------------------------------
// Flash attention (causal).  Block = (b, h, 128-row q tile), 4 warps.
// (unchanged — passing; next optimization target after GEMM)
// ---------------------------------------------------------------------------
#define KS_OFF (128 * GSA)
#define VS_OFF (KS_OFF + 2 * 64 * GSA)
#define KVSTGW (64 * GSA)
#define A_SMEM_BYTES ((VS_OFF + 2 * 64 * GSA) * 4)   // 55296

__global__ __launch_bounds__(128)
void attn_kernel(const __half* __restrict__ gq, const __half* __restrict__ gk,
                 const __half* __restrict__ gv, __half* __restrict__ gout)
{
    extern __shared__ unsigned smu[];
    unsigned* Ps = smu;
    const unsigned smem_byte = (unsigned)__cvta_generic_to_shared(smu);

    const int tid  = threadIdx.x;
    const int lane = tid & 31, w = tid >> 5;
    const int g = lane >> 2, t = lane & 3;
    const int qt = gridDim.x - 1 - blockIdx.x;
    const int h = blockIdx.y, b = blockIdx.z;

    const size_t base = (size_t)(b * NUM_HEADS + h) * SEQ * HEAD_DIM;
    const __half* Q  = gq + base + (size_t)qt * 128 * HEAD_DIM;
    const __half* Kp = gk + base;
    const __half* Vp = gv + base;

    for (int i = tid; i < 128 * 8; i += 128) {
        const int r = i >> 3, c8 = i & 7;
        uint4 v4 = reinterpret_cast<const uint4*>(Q + r * HEAD_DIM)[c8];
        *reinterpret_cast<uint4*>(&Ps[r * GSA + c8 * 4]) = v4;
    }
    __syncthreads();

    const unsigned amat_lane =
        (unsigned)((w * 32 + (lane & 15)) * GROWB + (lane >> 4) * 16);
    unsigned qf[4][2][4];
#pragma unroll
    for (int kk = 0; kk < 4; kk++)
#pragma unroll
        for (int mt = 0; mt < 2; mt++)
            ldsm4(qf[kk][mt][0], qf[kk][mt][1], qf[kk][mt][2], qf[kk][mt][3],
                  smem_byte + amat_lane + mt * 16 * GROWB + kk * 32);
    __syncthreads();

    float oacc[2][8][4];
#pragma unroll
    for (int mt = 0; mt < 2; mt++)
#pragma unroll
        for (int i = 0; i < 8; i++)
#pragma unroll
            for (int e = 0; e < 4; e++) oacc[mt][i][e] = 0.f;

    float mr[4], ls[4];
#pragma unroll
    for (int i = 0; i < 4; i++) { mr[i] = -1e30f; ls[i] = 0.f; }

    const float sl = 0.125f * 1.4426950408889634f;
    const int njt = 2 * qt + 2;

    auto issueKV = [&](int s, int j) {
        const __half* Kj = Kp + (size_t)j * 64 * HEAD_DIM;
        const __half* Vj = Vp + (size_t)j * 64 * HEAD_DIM;
        unsigned* dK = smu + KS_OFF + s * KVSTGW;
        unsigned* dV = smu + VS_OFF + s * KVSTGW;
#pragma unroll
        for (int i = 0; i < 4; i++) {
            const int lin = tid + i * 128;
            const int r = lin >> 3, c8 = lin & 7;
            cp16(dK + r * GSA + c8 * 4, Kj + r * HEAD_DIM + c8 * 8);
        }
#pragma unroll
        for (int i = 0; i < 4; i++) {
            const int lin = tid + i * 128;
            const int r = lin >> 3, c8 = lin & 7;
            cp16(dV + r * GSA + c8 * 4, Vj + r * HEAD_DIM + c8 * 8);
        }
        asm volatile("cp.async.commit_group;\n" ::: "memory");
    };

    const unsigned bmat_lane =
        (unsigned)((((lane >> 3) & 1) * 8 + (lane & 7)) * GROWB
                   + (lane >> 4) * 16);
    const unsigned vmat_lane =
        (unsigned)((((lane >> 3) & 1) * 8 + (lane & 7)) * GROWB
                   + (lane >> 4) * 16);

    issueKV(0, 0);
    for (int j = 0; j < njt; j++) {
        const int s = j & 1;
        if (j + 1 < njt) {
            issueKV(s ^ 1, j + 1);
            asm volatile("cp.async.wait_group 1;\n" ::: "memory");
        } else {
            asm volatile("cp.async.wait_group 0;\n" ::: "memory");
        }
        __syncthreads();

        const unsigned ksb = smem_byte + (KS_OFF + s * KVSTGW) * 4;
        const unsigned vsb = smem_byte + (VS_OFF + s * KVSTGW) * 4;

        float sacc[2][8][4];
#pragma unroll
        for (int mt = 0; mt < 2; mt++)
#pragma unroll
            for (int i = 0; i < 8; i++)
#pragma unroll
                for (int e = 0; e < 4; e++) sacc[mt][i][e] = 0.f;

#pragma unroll
        for (int kk = 0; kk < 4; kk++) {
            unsigned bf[8][2];
#pragma unroll
            for (int p = 0; p < 4; p++) {
                unsigned r0, r1, r2, r3;
                ldsm4(r0, r1, r2, r3,
                      ksb + bmat_lane + p * 16 * GROWB + kk * 32);
                bf[2 * p][0] = r0; bf[2 * p + 1][0] = r1;
                bf[2 * p][1] = r2; bf[2 * p + 1][1] = r3;
            }
#pragma unroll
            for (int nt = 0; nt < 8; nt++) {
                mma16(sacc[0][nt], qf[kk][0], bf[nt][0], bf[nt][1]);
                mma16(sacc[1][nt], qf[kk][1], bf[nt][0], bf[nt][1]);
            }
        }

        if (j >= 2 * qt) {
#pragma unroll
            for (int mt = 0; mt < 2; mt++)
#pragma unroll
                for (int nt = 0; nt < 8; nt++)
#pragma unroll
                    for (int e = 0; e < 4; e++) {
                        const int colg = j * 64 + nt * 8 + 2 * t + (e & 1);
                        const int rowg = qt * 128 + w * 32 + mt * 16 + g
                                       + ((e >> 1) << 3);
                        sacc[mt][nt][e] = (colg > rowg) ? -1e30f
                                                        : sacc[mt][nt][e] * sl;
                    }
        } else {
#pragma unroll
            for (int mt = 0; mt < 2; mt++)
#pragma unroll
                for (int nt = 0; nt < 8; nt++)
#pragma unroll
                    for (int e = 0; e < 4; e++) sacc[mt][nt][e] *= sl;
        }

#pragma unroll
        for (int mt = 0; mt < 2; mt++) {
            float mx0 = -1e30f, mx1 = -1e30f;
#pragma unroll
            for (int nt = 0; nt < 8; nt++) {
                mx0 = fmaxf(mx0, fmaxf(sacc[mt][nt][0], sacc[mt][nt][1]));
                mx1 = fmaxf(mx1, fmaxf(sacc[mt][nt][2], sacc[mt][nt][3]));
            }
            mx0 = fmaxf(mx0, __shfl_xor_sync(0xffffffffu, mx0, 1));
            mx0 = fmaxf(mx0, __shfl_xor_sync(0xffffffffu, mx0, 2));
            mx1 = fmaxf(mx1, __shfl_xor_sync(0xffffffffu, mx1, 1));
            mx1 = fmaxf(mx1, __shfl_xor_sync(0xffffffffu, mx1, 2));
            const float nm0 = fmaxf(mr[mt * 2 + 0], mx0);
            const float nm1 = fmaxf(mr[mt * 2 + 1], mx1);
            const float al0 = ex2f(mr[mt * 2 + 0] - nm0);
            const float al1 = ex2f(mr[mt * 2 + 1] - nm1);
            mr[mt * 2 + 0] = nm0; mr[mt * 2 + 1] = nm1;

            const int prow = w * 32 + mt * 16 + g;
            float ps0 = 0.f, ps1 = 0.f;
#pragma unroll
            for (int nt = 0; nt < 8; nt++) {
                const float p0 = ex2f(sacc[mt][nt][0] - nm0);
                const float p1 = ex2f(sacc[mt][nt][1] - nm0);
                const float p2 = ex2f(sacc[mt][nt][2] - nm1);
                const float p3 = ex2f(sacc[mt][nt][3] - nm1);
                ps0 += p0 + p1; ps1 += p2 + p3;
                Ps[ prow      * GSA + nt * 4 + t] = h2u(__floats2half2_rn(p0, p1));
                Ps[(prow + 8) * GSA + nt * 4 + t] = h2u(__floats2half2_rn(p2, p3));
            }
            ps0 += __shfl_xor_sync(0xffffffffu, ps0, 1);
            ps0 += __shfl_xor_sync(0xffffffffu, ps0, 2);
            ps1 += __shfl_xor_sync(0xffffffffu, ps1, 1);
            ps1 += __shfl_xor_sync(0xffffffffu, ps1, 2);
            ls[mt * 2 + 0] = ls[mt * 2 + 0] * al0 + ps0;
            ls[mt * 2 + 1] = ls[mt * 2 + 1] * al1 + ps1;
#pragma unroll
            for (int nt = 0; nt < 8; nt++) {
                oacc[mt][nt][0] *= al0; oacc[mt][nt][1] *= al0;
                oacc[mt][nt][2] *= al1; oacc[mt][nt][3] *= al1;
            }
        }
        __syncwarp();

#pragma unroll
        for (int kk = 0; kk < 4; kk++) {
            unsigned pa[2][4];
#pragma unroll
            for (int mt = 0; mt < 2; mt++)
                ldsm4(pa[mt][0], pa[mt][1], pa[mt][2], pa[mt][3],
                      smem_byte + amat_lane + mt * 16 * GROWB + kk * 32);
#pragma unroll
            for (int p = 0; p < 4; p++) {
                unsigned r0, r1, r2, r3;
                ldsm4t(r0, r1, r2, r3,
                       vsb + (unsigned)(kk * 16) * GROWB + vmat_lane
                           + (unsigned)(2 * p) * 16);
                mma16(oacc[0][2 * p    ], pa[0], r0, r1);
                mma16(oacc[1][2 * p    ], pa[1], r0, r1);
                mma16(oacc[0][2 * p + 1], pa[0], r2, r3);
                mma16(oacc[1][2 * p + 1], pa[1], r2, r3);
            }
        }
        __syncthreads();
    }

#pragma unroll
    for (int mt = 0; mt < 2; mt++) {
        const float il0 = 1.f / ls[mt * 2 + 0];
        const float il1 = 1.f / ls[mt * 2 + 1];
        const int qrow = qt * 128 + w * 32 + mt * 16 + g;
        __half* O0 = gout + (size_t)(b * SEQ + qrow) * D_MODEL + h * HEAD_DIM;
        __half* O1 = O0 + 8 * D_MODEL;
#pragma unroll
        for (int nt = 0; nt < 8; nt++) {
            const int col = nt * 8 + 2 * t;
            *reinterpret_cast<unsigned*>(O0 + col) =
                h2u(__floats2half2_rn(oacc[mt][nt][0] * il0,
                                      oacc[mt][nt][1] * il0));
            *reinterpret_cast<unsigned*>(O1 + col) =
                h2u(__floats2half2_rn(oacc[mt][nt][2] * il1,
                                      oacc[mt][nt][3] * il1));
        }
    }
}

// ---------------------------------------------------------------------------
// Launch
// ---------------------------------------------------------------------------
extern "C" void kernel_launch(void* const* d_in, const int* in_sizes, int n_in,
                              void* d_out, int out_size)
{
    const float* x  = (const float*)d_in[0];
    const float* Wq = (const float*)d_in[1];
    const float* bq = (const float*)d_in[2];
    const float* Wk = (const float*)d_in[3];
    const float* bk = (const float*)d_in[4];
    const float* Wv = (const float*)d_in[5];
    const float* bv = (const float*)d_in[6];
    const float* Wo = (const float*)d_in[7];
    const float* bo = (const float*)d_in[8];
    float* out = (float*)d_out;

    __half *q, *k, *v, *ao, *xh, *wq, *wk, *wv, *wo;
    cudaGetSymbolAddress((void**)&q,  g_q);
    cudaGetSymbolAddress((void**)&k,  g_k);
    cudaGetSymbolAddress((void**)&v,  g_v);
    cudaGetSymbolAddress((void**)&ao, g_ao);
    cudaGetSymbolAddress((void**)&xh, g_xh);
    cudaGetSymbolAddress((void**)&wq, g_wq);
    cudaGetSymbolAddress((void**)&wk, g_wk);
    cudaGetSymbolAddress((void**)&wv, g_wv);
    cudaGetSymbolAddress((void**)&wo, g_wo);

    to_half_all<<<2048, 256>>>((const float4*)x,  (const float4*)Wq,
                               (const float4*)Wk, (const float4*)Wv,
                               (const float4*)Wo,
                               (uint2*)xh, (uint2*)wq, (uint2*)wk,
                               (uint2*)wv, (uint2*)wo);

    cudaFuncSetAttribute(gemm_h<0>,
        cudaFuncAttributeMaxDynamicSharedMemorySize, GSMEM_BYTES);
    cudaFuncSetAttribute(gemm_h<1>,
        cudaFuncAttributeMaxDynamicSharedMemorySize, GSMEM_BYTES);
    cudaFuncSetAttribute(attn_kernel,
        cudaFuncAttributeMaxDynamicSharedMemorySize, A_SMEM_BYTES);

    // fused QKV: 24 x 32 = 768 CTAs (wsel = blockIdx.x >> 3)
    const dim3 qkvgrid(3 * D_MODEL / 128, MTOT / 128);
    gemm_h<1><<<qkvgrid, 128, GSMEM_BYTES>>>(
        xh, wq, wk, wv, bq, bk, bv, q, k, v);

    const dim3 agrid(SEQ / 128, NUM_HEADS, BATCH);
    attn_kernel<<<agrid, 128, A_SMEM_BYTES>>>(q, k, v, ao);

    const dim3 ogrid(D_MODEL / 128, MTOT / 128);   // 8 x 32 = 256 CTAs
    gemm_h<0><<<ogrid, 128, GSMEM_BYTES>>>(
        ao, wo, wo, wo, bo, bo, bo, out, out, out);
}

// round 8
// speedup vs baseline: 1.1742x; 1.1382x over previous
#include <cuda_runtime.h>
#include <cuda_fp16.h>
#include <cstdint>

#define D_MODEL   1024
#define NUM_HEADS 16
#define HEAD_DIM  64
#define SEQ       2048
#define BATCH     2
#define MTOT      (BATCH * SEQ)

// ---------------------------------------------------------------------------
// Scratch (device globals; allocation forbidden)
// ---------------------------------------------------------------------------
__device__ __half g_q [BATCH * NUM_HEADS * SEQ * HEAD_DIM];
__device__ __half g_k [BATCH * NUM_HEADS * SEQ * HEAD_DIM];
__device__ __half g_v [BATCH * NUM_HEADS * SEQ * HEAD_DIM];
__device__ __half g_ao[MTOT * D_MODEL];
__device__ __half g_xh[MTOT * D_MODEL];
__device__ __half g_wq[D_MODEL * D_MODEL];
__device__ __half g_wk[D_MODEL * D_MODEL];
__device__ __half g_wv[D_MODEL * D_MODEL];
__device__ __half g_wo[D_MODEL * D_MODEL];

// ---------------------------------------------------------------------------
// Helpers
// ---------------------------------------------------------------------------
__device__ __forceinline__ float ex2f(float x) {
    float y;
    asm("ex2.approx.f32 %0, %1;" : "=f"(y) : "f"(x));
    return y;
}

__device__ __forceinline__ void mma16(float c[4], const unsigned a[4],
                                      unsigned b0, unsigned b1) {
    asm volatile(
        "mma.sync.aligned.m16n8k16.row.col.f32.f16.f16.f32 "
        "{%0,%1,%2,%3},{%4,%5,%6,%7},{%8,%9},{%0,%1,%2,%3};"
        : "+f"(c[0]), "+f"(c[1]), "+f"(c[2]), "+f"(c[3])
        : "r"(a[0]), "r"(a[1]), "r"(a[2]), "r"(a[3]), "r"(b0), "r"(b1));
}

__device__ __forceinline__ void cp16(void* sdst, const void* gsrc) {
    unsigned s = (unsigned)__cvta_generic_to_shared(sdst);
    asm volatile("cp.async.cg.shared.global [%0], [%1], 16;\n"
                 :: "r"(s), "l"(gsrc));
}

__device__ __forceinline__ void ldsm4(unsigned& r0, unsigned& r1,
                                      unsigned& r2, unsigned& r3,
                                      unsigned addr) {
    asm volatile(
        "ldmatrix.sync.aligned.m8n8.x4.shared.b16 {%0,%1,%2,%3}, [%4];"
        : "=r"(r0), "=r"(r1), "=r"(r2), "=r"(r3) : "r"(addr));
}

__device__ __forceinline__ void ldsm4t(unsigned& r0, unsigned& r1,
                                       unsigned& r2, unsigned& r3,
                                       unsigned addr) {
    asm volatile(
        "ldmatrix.sync.aligned.m8n8.x4.trans.shared.b16 {%0,%1,%2,%3}, [%4];"
        : "=r"(r0), "=r"(r1), "=r"(r2), "=r"(r3) : "r"(addr));
}

__device__ __forceinline__ unsigned h2u(__half2 h) {
    return *reinterpret_cast<unsigned*>(&h);
}

// ---------------------------------------------------------------------------
// Fused fp32 -> fp16 convert
// ---------------------------------------------------------------------------
#define NX4 (MTOT * D_MODEL / 4)
#define NW4 (D_MODEL * D_MODEL / 4)

__global__ void to_half_all(
    const float4* __restrict__ x,  const float4* __restrict__ wq,
    const float4* __restrict__ wk, const float4* __restrict__ wv,
    const float4* __restrict__ wo,
    uint2* __restrict__ xh, uint2* __restrict__ oq, uint2* __restrict__ ok,
    uint2* __restrict__ ov, uint2* __restrict__ oo)
{
    const int total = NX4 + 4 * NW4;
    for (int i = blockIdx.x * blockDim.x + threadIdx.x; i < total;
         i += gridDim.x * blockDim.x) {
        const float4* src;
        uint2* dst;
        int off;
        if (i < NX4) { src = x; dst = xh; off = i; }
        else {
            const int j = i - NX4, w = j >> 18;
            off = j & (NW4 - 1);
            src = (w == 0) ? wq : (w == 1) ? wk : (w == 2) ? wv : wo;
            dst = (w == 0) ? oq : (w == 1) ? ok : (w == 2) ? ov : oo;
        }
        float4 v = src[off];
        uint2 o;
        o.x = h2u(__floats2half2_rn(v.x, v.y));
        o.y = h2u(__floats2half2_rn(v.z, v.w));
        dst[off] = o;
    }
}

// ---------------------------------------------------------------------------
// NT GEMM (fp16 in / fp32 accum): C[m,n] = sum_k A[m,k]*W[n,k] + bias[n]
// CTA tile 128x128, 4 warps (2x2), warp tile 64x64, 3-stage cp.async ring,
// one __syncthreads per chunk, next-stage cp.asyncs SPREAD across kk steps.
// QKV=1: blockIdx.x = wsel*8 + ntile; fp16 scatter to [B,H,S,hd].
// QKV=0: fp32 row-major out.
// ---------------------------------------------------------------------------
#define GSA    36                          // words per 64-half row (+pad)
#define GROWB  144                         // bytes per row
#define STAGEW ((128 + 128) * GSA)         // 9216 words per stage
#define NSTG   3
#define GSMEM_BYTES (NSTG * STAGEW * 4)    // 110592

template <int QKV>
__global__ __launch_bounds__(128, 2)
void gemm_h(const __half* __restrict__ A,
            const __half* __restrict__ W0, const __half* __restrict__ W1,
            const __half* __restrict__ W2,
            const float* __restrict__ b0p, const float* __restrict__ b1p,
            const float* __restrict__ b2p,
            void* __restrict__ C0, void* __restrict__ C1,
            void* __restrict__ C2)
{
    extern __shared__ unsigned sm[];
    const unsigned smem_byte = (unsigned)__cvta_generic_to_shared(sm);
    const int tid = threadIdx.x, lane = tid & 31, wid = tid >> 5;
    const int wm = wid & 1, wn = wid >> 1;            // 2 x 2 warps
    const int m0 = blockIdx.y * 128;

    const int wsel = QKV ? (blockIdx.x >> 3) : 0;
    const int n0   = QKV ? (blockIdx.x & 7) * 128 : blockIdx.x * 128;
    const __half* W = (wsel == 0) ? W0 : (wsel == 1) ? W1 : W2;
    const float* bias = (wsel == 0) ? b0p : (wsel == 1) ? b1p : b2p;
    void* Cv = (wsel == 0) ? C0 : (wsel == 1) ? C1 : C2;

    float acc[4][8][4];
#pragma unroll
    for (int i = 0; i < 4; i++)
#pragma unroll
        for (int j = 0; j < 8; j++)
#pragma unroll
            for (int e = 0; e < 4; e++) acc[i][j][e] = 0.f;

    // part = 0..3: two row-bundles of A and B each (spreadable issue)
    auto issue_part = [&](int s, int k0, int part) {
        unsigned* dA = sm + s * STAGEW;
        unsigned* dB = dA + 128 * GSA;
        const __half* Ap = A + (size_t)m0 * D_MODEL + k0;
        const __half* Bp = W + (size_t)n0 * D_MODEL + k0;
#pragma unroll
        for (int i = 2 * part; i < 2 * part + 2; i++) {
            const int lin = tid + i * 128;
            const int r = lin >> 3, c8 = lin & 7;
            cp16(dA + r * GSA + c8 * 4, Ap + (size_t)r * D_MODEL + c8 * 8);
            cp16(dB + r * GSA + c8 * 4, Bp + (size_t)r * D_MODEL + c8 * 8);
        }
    };
    auto issue_full = [&](int s, int k0) {
#pragma unroll
        for (int p = 0; p < 4; p++) issue_part(s, k0, p);
        asm volatile("cp.async.commit_group;\n" ::: "memory");
    };

    const unsigned a_lane =
        (unsigned)((wm * 64 + (lane & 15)) * GROWB + (lane >> 4) * 16);
    const unsigned b_lane =
        (unsigned)((wn * 64 + ((lane >> 3) & 1) * 8 + (lane & 7)) * GROWB
                   + (lane >> 4) * 16);

    issue_full(0, 0);
    issue_full(1, 64);
    const int T = D_MODEL / 64;   // 16 chunks
    for (int tt = 0; tt < T; tt++) {
        const int s = tt % NSTG;
        if (tt + 1 < T) {
            asm volatile("cp.async.wait_group 1;\n" ::: "memory");
        } else {
            asm volatile("cp.async.wait_group 0;\n" ::: "memory");
        }
        __syncthreads();   // stage tt ready AND all warps done with tt-1
        const bool pf = (tt + 2 < T);
        const int ps = (tt + 2) % NSTG, pk = (tt + 2) * 64;

        const unsigned aBase = smem_byte + s * STAGEW * 4 + a_lane;
        const unsigned bBase = smem_byte + s * STAGEW * 4 + 128 * GROWB + b_lane;
#pragma unroll
        for (int kk = 0; kk < 4; kk++) {
            if (pf) issue_part(ps, pk, kk);   // spread LDGSTS across kk steps
            unsigned af[4][4], bf[8][2];
#pragma unroll
            for (int mt = 0; mt < 4; mt++)
                ldsm4(af[mt][0], af[mt][1], af[mt][2], af[mt][3],
                      aBase + mt * 16 * GROWB + kk * 32);
#pragma unroll
            for (int p = 0; p < 4; p++) {
                unsigned r0, r1, r2, r3;
                ldsm4(r0, r1, r2, r3, bBase + p * 16 * GROWB + kk * 32);
                bf[2 * p][0] = r0; bf[2 * p + 1][0] = r1;
                bf[2 * p][1] = r2; bf[2 * p + 1][1] = r3;
            }
#pragma unroll
            for (int mt = 0; mt < 4; mt++)
#pragma unroll
                for (int nt = 0; nt < 8; nt++)
                    mma16(acc[mt][nt], af[mt], bf[nt][0], bf[nt][1]);
        }
        if (pf) asm volatile("cp.async.commit_group;\n" ::: "memory");
    }

    // epilogue
    const int g = lane >> 2, t = lane & 3;
#pragma unroll
    for (int mt = 0; mt < 4; mt++) {
#pragma unroll
        for (int nt = 0; nt < 8; nt++) {
            const int row = m0 + wm * 64 + mt * 16 + g;
            const int col = n0 + wn * 64 + nt * 8 + 2 * t;
            const float bv0 = bias[col], bv1 = bias[col + 1];
#pragma unroll
            for (int hf = 0; hf < 2; hf++) {
                const int r = row + hf * 8;
                const float vx = acc[mt][nt][hf * 2 + 0] + bv0;
                const float vy = acc[mt][nt][hf * 2 + 1] + bv1;
                if (QKV == 0) {
                    float* C = (float*)Cv;
                    *reinterpret_cast<float2*>(C + (size_t)r * D_MODEL + col) =
                        make_float2(vx, vy);
                } else {
                    __half* C = (__half*)Cv;
                    const int bb = r >> 11, ss = r & (SEQ - 1);
                    const int hh = col >> 6, dd = col & (HEAD_DIM - 1);
                    *reinterpret_cast<unsigned*>(
                        C + (((size_t)(bb * NUM_HEADS + hh) * SEQ + ss) << 6)
                          + dd) = h2u(__floats2half2_rn(vx, vy));
                }
            }
        }
    }
}

// ---------------------------------------------------------------------------
// Flash attention (causal).  Block = (b, h, 128-row q tile), 4 warps.
// P lives in REGISTERS: the S-mma C-fragment layout equals the PV-mma
// A-fragment layout (c0..c3 of nt=2kk/2kk+1 pack into a0..a3) -> no P smem
// round-trip.  smem: [K0][K1][V0][V1], 2-stage cp.async; Q staged through
// K0+K1 once at start, then in registers.
// ---------------------------------------------------------------------------
#define KVSTGW (64 * GSA)                    // words per K or V stage
#define AVS_OFF (2 * KVSTGW)                 // V stages start
#define A_SMEM_BYTES (4 * KVSTGW * 4)        // 36864

__global__ __launch_bounds__(128, 2)
void attn_kernel(const __half* __restrict__ gq, const __half* __restrict__ gk,
                 const __half* __restrict__ gv, __half* __restrict__ gout)
{
    extern __shared__ unsigned smu[];
    const unsigned smem_byte = (unsigned)__cvta_generic_to_shared(smu);

    const int tid  = threadIdx.x;
    const int lane = tid & 31, w = tid >> 5;
    const int g = lane >> 2, t = lane & 3;
    const int qt = gridDim.x - 1 - blockIdx.x;    // long blocks first
    const int h = blockIdx.y, b = blockIdx.z;

    const size_t base = (size_t)(b * NUM_HEADS + h) * SEQ * HEAD_DIM;
    const __half* Q  = gq + base + (size_t)qt * 128 * HEAD_DIM;
    const __half* Kp = gk + base;
    const __half* Vp = gv + base;

    // ---- stage Q through K0+K1 region (exactly 128 rows * 144B) ----
    for (int i = tid; i < 128 * 8; i += 128) {
        const int r = i >> 3, c8 = i & 7;
        uint4 v4 = reinterpret_cast<const uint4*>(Q + r * HEAD_DIM)[c8];
        *reinterpret_cast<uint4*>(&smu[r * GSA + c8 * 4]) = v4;
    }
    __syncthreads();

    const unsigned amat_lane =
        (unsigned)((w * 32 + (lane & 15)) * GROWB + (lane >> 4) * 16);
    unsigned qf[4][2][4];   // [kk][mt][frag]
#pragma unroll
    for (int kk = 0; kk < 4; kk++)
#pragma unroll
        for (int mt = 0; mt < 2; mt++)
            ldsm4(qf[kk][mt][0], qf[kk][mt][1], qf[kk][mt][2], qf[kk][mt][3],
                  smem_byte + amat_lane + mt * 16 * GROWB + kk * 32);
    __syncthreads();   // K0/K1 free for the KV pipeline

    float oacc[2][8][4];
#pragma unroll
    for (int mt = 0; mt < 2; mt++)
#pragma unroll
        for (int i = 0; i < 8; i++)
#pragma unroll
            for (int e = 0; e < 4; e++) oacc[mt][i][e] = 0.f;

    float mr[4], ls[4];
#pragma unroll
    for (int i = 0; i < 4; i++) { mr[i] = -1e30f; ls[i] = 0.f; }

    const float sl = 0.125f * 1.4426950408889634f;   // SCALE * log2(e)
    const int njt = 2 * qt + 2;

    auto issueKV = [&](int s, int j) {
        const __half* Kj = Kp + (size_t)j * 64 * HEAD_DIM;
        const __half* Vj = Vp + (size_t)j * 64 * HEAD_DIM;
        unsigned* dK = smu + s * KVSTGW;
        unsigned* dV = smu + AVS_OFF + s * KVSTGW;
#pragma unroll
        for (int i = 0; i < 4; i++) {
            const int lin = tid + i * 128;
            const int r = lin >> 3, c8 = lin & 7;
            cp16(dK + r * GSA + c8 * 4, Kj + r * HEAD_DIM + c8 * 8);
        }
#pragma unroll
        for (int i = 0; i < 4; i++) {
            const int lin = tid + i * 128;
            const int r = lin >> 3, c8 = lin & 7;
            cp16(dV + r * GSA + c8 * 4, Vj + r * HEAD_DIM + c8 * 8);
        }
        asm volatile("cp.async.commit_group;\n" ::: "memory");
    };

    const unsigned bmat_lane =
        (unsigned)((((lane >> 3) & 1) * 8 + (lane & 7)) * GROWB
                   + (lane >> 4) * 16);

    issueKV(0, 0);
    for (int j = 0; j < njt; j++) {
        const int s = j & 1;
        if (j + 1 < njt) {
            issueKV(s ^ 1, j + 1);
            asm volatile("cp.async.wait_group 1;\n" ::: "memory");
        } else {
            asm volatile("cp.async.wait_group 0;\n" ::: "memory");
        }
        __syncthreads();

        const unsigned ksb = smem_byte + (unsigned)(s * KVSTGW) * 4;
        const unsigned vsb = smem_byte + (unsigned)(AVS_OFF + s * KVSTGW) * 4;

        // ---- S = Q K^T ----
        float sacc[2][8][4];
#pragma unroll
        for (int mt = 0; mt < 2; mt++)
#pragma unroll
            for (int i = 0; i < 8; i++)
#pragma unroll
                for (int e = 0; e < 4; e++) sacc[mt][i][e] = 0.f;

#pragma unroll
        for (int kk = 0; kk < 4; kk++) {
            unsigned bf[8][2];
#pragma unroll
            for (int p = 0; p < 4; p++) {
                unsigned r0, r1, r2, r3;
                ldsm4(r0, r1, r2, r3,
                      ksb + bmat_lane + p * 16 * GROWB + kk * 32);
                bf[2 * p][0] = r0; bf[2 * p + 1][0] = r1;
                bf[2 * p][1] = r2; bf[2 * p + 1][1] = r3;
            }
#pragma unroll
            for (int nt = 0; nt < 8; nt++) {
                mma16(sacc[0][nt], qf[kk][0], bf[nt][0], bf[nt][1]);
                mma16(sacc[1][nt], qf[kk][1], bf[nt][0], bf[nt][1]);
            }
        }

        // ---- scale + causal mask on diagonal tiles ----
        if (j >= 2 * qt) {
#pragma unroll
            for (int mt = 0; mt < 2; mt++)
#pragma unroll
                for (int nt = 0; nt < 8; nt++)
#pragma unroll
                    for (int e = 0; e < 4; e++) {
                        const int colg = j * 64 + nt * 8 + 2 * t + (e & 1);
                        const int rowg = qt * 128 + w * 32 + mt * 16 + g
                                       + ((e >> 1) << 3);
                        sacc[mt][nt][e] = (colg > rowg) ? -1e30f
                                                        : sacc[mt][nt][e] * sl;
                    }
        } else {
#pragma unroll
            for (int mt = 0; mt < 2; mt++)
#pragma unroll
                for (int nt = 0; nt < 8; nt++)
#pragma unroll
                    for (int e = 0; e < 4; e++) sacc[mt][nt][e] *= sl;
        }

        // ---- online softmax; pack P straight into A-fragments ----
        unsigned pp[2][8][2];   // [mt][nt][lo(row g) / hi(row g+8)]
#pragma unroll
        for (int mt = 0; mt < 2; mt++) {
            float mx0 = -1e30f, mx1 = -1e30f;
#pragma unroll
            for (int nt = 0; nt < 8; nt++) {
                mx0 = fmaxf(mx0, fmaxf(sacc[mt][nt][0], sacc[mt][nt][1]));
                mx1 = fmaxf(mx1, fmaxf(sacc[mt][nt][2], sacc[mt][nt][3]));
            }
            mx0 = fmaxf(mx0, __shfl_xor_sync(0xffffffffu, mx0, 1));
            mx0 = fmaxf(mx0, __shfl_xor_sync(0xffffffffu, mx0, 2));
            mx1 = fmaxf(mx1, __shfl_xor_sync(0xffffffffu, mx1, 1));
            mx1 = fmaxf(mx1, __shfl_xor_sync(0xffffffffu, mx1, 2));
            const float nm0 = fmaxf(mr[mt * 2 + 0], mx0);
            const float nm1 = fmaxf(mr[mt * 2 + 1], mx1);
            const float al0 = ex2f(mr[mt * 2 + 0] - nm0);
            const float al1 = ex2f(mr[mt * 2 + 1] - nm1);
            mr[mt * 2 + 0] = nm0; mr[mt * 2 + 1] = nm1;

            float ps0 = 0.f, ps1 = 0.f;
#pragma unroll
            for (int nt = 0; nt < 8; nt++) {
                const float p0 = ex2f(sacc[mt][nt][0] - nm0);
                const float p1 = ex2f(sacc[mt][nt][1] - nm0);
                const float p2 = ex2f(sacc[mt][nt][2] - nm1);
                const float p3 = ex2f(sacc[mt][nt][3] - nm1);
                ps0 += p0 + p1; ps1 += p2 + p3;
                pp[mt][nt][0] = h2u(__floats2half2_rn(p0, p1));
                pp[mt][nt][1] = h2u(__floats2half2_rn(p2, p3));
            }
            ps0 += __shfl_xor_sync(0xffffffffu, ps0, 1);
            ps0 += __shfl_xor_sync(0xffffffffu, ps0, 2);
            ps1 += __shfl_xor_sync(0xffffffffu, ps1, 1);
            ps1 += __shfl_xor_sync(0xffffffffu, ps1, 2);
            ls[mt * 2 + 0] = ls[mt * 2 + 0] * al0 + ps0;
            ls[mt * 2 + 1] = ls[mt * 2 + 1] * al1 + ps1;
#pragma unroll
            for (int nt = 0; nt < 8; nt++) {
                oacc[mt][nt][0] *= al0; oacc[mt][nt][1] *= al0;
                oacc[mt][nt][2] *= al1; oacc[mt][nt][3] *= al1;
            }
        }

        // ---- O += P V  (A from registers, B = V^T via ldmatrix.trans) ----
#pragma unroll
        for (int kk = 0; kk < 4; kk++) {
            const unsigned pa0[4] = { pp[0][2 * kk][0], pp[0][2 * kk][1],
                                      pp[0][2 * kk + 1][0], pp[0][2 * kk + 1][1] };
            const unsigned pa1[4] = { pp[1][2 * kk][0], pp[1][2 * kk][1],
                                      pp[1][2 * kk + 1][0], pp[1][2 * kk + 1][1] };
#pragma unroll
            for (int p = 0; p < 4; p++) {
                unsigned r0, r1, r2, r3;
                ldsm4t(r0, r1, r2, r3,
                       vsb + (unsigned)(kk * 16) * GROWB + bmat_lane
                           + (unsigned)(2 * p) * 16);
                mma16(oacc[0][2 * p    ], pa0, r0, r1);
                mma16(oacc[1][2 * p    ], pa1, r0, r1);
                mma16(oacc[0][2 * p + 1], pa0, r2, r3);
                mma16(oacc[1][2 * p + 1], pa1, r2, r3);
            }
        }
        __syncthreads();   // all warps done with stage s before refill
    }

    // ---- epilogue ----
#pragma unroll
    for (int mt = 0; mt < 2; mt++) {
        const float il0 = 1.f / ls[mt * 2 + 0];
        const float il1 = 1.f / ls[mt * 2 + 1];
        const int qrow = qt * 128 + w * 32 + mt * 16 + g;
        __half* O0 = gout + (size_t)(b * SEQ + qrow) * D_MODEL + h * HEAD_DIM;
        __half* O1 = O0 + 8 * D_MODEL;
#pragma unroll
        for (int nt = 0; nt < 8; nt++) {
            const int col = nt * 8 + 2 * t;
            *reinterpret_cast<unsigned*>(O0 + col) =
                h2u(__floats2half2_rn(oacc[mt][nt][0] * il0,
                                      oacc[mt][nt][1] * il0));
            *reinterpret_cast<unsigned*>(O1 + col) =
                h2u(__floats2half2_rn(oacc[mt][nt][2] * il1,
                                      oacc[mt][nt][3] * il1));
        }
    }
}

// ---------------------------------------------------------------------------
// Launch
// ---------------------------------------------------------------------------
extern "C" void kernel_launch(void* const* d_in, const int* in_sizes, int n_in,
                              void* d_out, int out_size)
{
    const float* x  = (const float*)d_in[0];
    const float* Wq = (const float*)d_in[1];
    const float* bq = (const float*)d_in[2];
    const float* Wk = (const float*)d_in[3];
    const float* bk = (const float*)d_in[4];
    const float* Wv = (const float*)d_in[5];
    const float* bv = (const float*)d_in[6];
    const float* Wo = (const float*)d_in[7];
    const float* bo = (const float*)d_in[8];
    float* out = (float*)d_out;

    __half *q, *k, *v, *ao, *xh, *wq, *wk, *wv, *wo;
    cudaGetSymbolAddress((void**)&q,  g_q);
    cudaGetSymbolAddress((void**)&k,  g_k);
    cudaGetSymbolAddress((void**)&v,  g_v);
    cudaGetSymbolAddress((void**)&ao, g_ao);
    cudaGetSymbolAddress((void**)&xh, g_xh);
    cudaGetSymbolAddress((void**)&wq, g_wq);
    cudaGetSymbolAddress((void**)&wk, g_wk);
    cudaGetSymbolAddress((void**)&wv, g_wv);
    cudaGetSymbolAddress((void**)&wo, g_wo);

    to_half_all<<<2048, 256>>>((const float4*)x,  (const float4*)Wq,
                               (const float4*)Wk, (const float4*)Wv,
                               (const float4*)Wo,
                               (uint2*)xh, (uint2*)wq, (uint2*)wk,
                               (uint2*)wv, (uint2*)wo);

    cudaFuncSetAttribute(gemm_h<0>,
        cudaFuncAttributeMaxDynamicSharedMemorySize, GSMEM_BYTES);
    cudaFuncSetAttribute(gemm_h<1>,
        cudaFuncAttributeMaxDynamicSharedMemorySize, GSMEM_BYTES);
    cudaFuncSetAttribute(attn_kernel,
        cudaFuncAttributeMaxDynamicSharedMemorySize, A_SMEM_BYTES);

    // fused QKV: 24 x 32 = 768 CTAs (wsel = blockIdx.x >> 3)
    const dim3 qkvgrid(3 * D_MODEL / 128, MTOT / 128);
    gemm_h<1><<<qkvgrid, 128, GSMEM_BYTES>>>(
        xh, wq, wk, wv, bq, bk, bv, q, k, v);

    const dim3 agrid(SEQ / 128, NUM_HEADS, BATCH);
    attn_kernel<<<agrid, 128, A_SMEM_BYTES>>>(q, k, v, ao);

    const dim3 ogrid(D_MODEL / 128, MTOT / 128);   // 8 x 32 = 256 CTAs
    gemm_h<0><<<ogrid, 128, GSMEM_BYTES>>>(
        ao, wo, wo, wo, bo, bo, bo, out, out, out);
}